// round 1
// baseline (speedup 1.0000x reference)
#include <cuda_runtime.h>
#include <math.h>

// out[t,b] = G(x[t,b]) where G is a scalar function (input feature dim = 1,
// zero-state LSTM cells). Strategy: build a table of G on a fine grid, then
// Catmull-Rom cubic interpolation for all 409600 elements.

#define NINT  8192                 // number of interpolation intervals
#define NT    (NINT + 3)           // table entries: node k at x = XMIN + (k-1)*H
#define XMIN  (-8.0f)
#define HSTEP (16.0f / 8192.0f)    // 0.001953125
#define INVH  (512.0f)

__device__ float g_table[8224];    // >= NT, __device__ global scratch (no malloc)

__device__ __forceinline__ float sigm(float v) {
    return 1.0f / (1.0f + __expf(-v));
}

// ---------------------------------------------------------------------------
// Kernel 1: build table. One block of 256 threads handles 32 nodes
// (node = blockIdx.x*32 + lane). Weights for layer-2 (i,g,o gates only; the
// f gate is dead because c_prev = 0) are staged into shared as float4 so the
// inner loop is one broadcast LDS.128 + one LDS + 3 FFMA per k.
// ---------------------------------------------------------------------------
__global__ void build_table_kernel(
    const float* __restrict__ w_ih1,  // [204,1]
    const float* __restrict__ b_ih1,  // [204]
    const float* __restrict__ b_hh1,  // [204]
    const float* __restrict__ w_ih2,  // [204,51]
    const float* __restrict__ b_ih2,  // [204]
    const float* __restrict__ b_hh2,  // [204]
    const float* __restrict__ w_lin,  // [51]
    const float* __restrict__ b_lin)  // [1]
{
    __shared__ float4 sh_w[51 * 51];     // (wi, wg, wo, 0) for (j,k)
    __shared__ float  sh_h1[51 * 32];    // h1[k] for each of 32 nodes (lane)
    __shared__ float  sh_out[32];

    const int t    = threadIdx.x;
    const int lane = t & 31;
    const int wrp  = t >> 5;

    // stage layer-2 weights (rows: i = j, g = 102+j, o = 153+j)
    for (int idx = t; idx < 51 * 51; idx += 256) {
        float4 v;
        v.x = w_ih2[idx];                 // i-gate rows 0..50
        v.y = w_ih2[idx + 102 * 51];      // g-gate rows 102..152
        v.z = w_ih2[idx + 153 * 51];      // o-gate rows 153..203
        v.w = 0.0f;
        sh_w[idx] = v;
    }
    if (t < 32) sh_out[t] = 0.0f;

    // phase 1: h1 for this lane's node. thread (wrp,lane) covers k = wrp, wrp+8, ...
    const int node = blockIdx.x * 32 + lane;
    const float xv = XMIN + (float)(node - 1) * HSTEP;
    for (int k = wrp; k < 51; k += 8) {
        float gi = fmaf(xv, w_ih1[k],       b_ih1[k]       + b_hh1[k]);
        float gg = fmaf(xv, w_ih1[102 + k], b_ih1[102 + k] + b_hh1[102 + k]);
        float go = fmaf(xv, w_ih1[153 + k], b_ih1[153 + k] + b_hh1[153 + k]);
        float c  = sigm(gi) * tanhf(gg);
        sh_h1[k * 32 + lane] = sigm(go) * tanhf(c);
    }
    __syncthreads();

    // phase 2: layer-2 gates + head. warp w handles j = w, w+8, ...
    float part = 0.0f;
    for (int j = wrp; j < 51; j += 8) {
        float ai = b_ih2[j]       + b_hh2[j];
        float ag = b_ih2[102 + j] + b_hh2[102 + j];
        float ao = b_ih2[153 + j] + b_hh2[153 + j];
        const float4* wrow = sh_w + j * 51;
        #pragma unroll
        for (int k = 0; k < 51; ++k) {
            float4 w = wrow[k];                 // broadcast across lanes
            float  h = sh_h1[k * 32 + lane];    // conflict-free
            ai = fmaf(w.x, h, ai);
            ag = fmaf(w.y, h, ag);
            ao = fmaf(w.z, h, ao);
        }
        float c2 = sigm(ai) * tanhf(ag);
        part = fmaf(sigm(ao) * tanhf(c2), w_lin[j], part);
    }
    atomicAdd(&sh_out[lane], part);
    __syncthreads();

    if (t < 32) {
        int n = blockIdx.x * 32 + t;
        if (n < NT) g_table[n] = sh_out[t] + b_lin[0];
    }
}

// ---------------------------------------------------------------------------
// Kernel 2: Catmull-Rom interpolation, float4 I/O (4 elements per thread).
// ---------------------------------------------------------------------------
__device__ __forceinline__ float interp_one(float x) {
    float u  = (x - XMIN) * INVH;           // node coordinate
    int   i0 = (int)floorf(u);
    i0 = min(max(i0, 0), NINT - 1);
    float tt = u - (float)i0;
    tt = fminf(fmaxf(tt, 0.0f), 1.0f);
    const float* tb = g_table + i0;         // nodes i0-1 .. i0+2
    float p0 = tb[0], p1 = tb[1], p2 = tb[2], p3 = tb[3];
    return p1 + 0.5f * (tt * ((p2 - p0)
              + tt * ((2.0f * p0 - 5.0f * p1 + 4.0f * p2 - p3)
              + tt * (3.0f * (p1 - p2) + p3 - p0))));
}

__global__ void interp_kernel(const float* __restrict__ x,
                              float* __restrict__ out, int n4)
{
    int i = blockIdx.x * blockDim.x + threadIdx.x;
    if (i >= n4) return;
    float4 v = reinterpret_cast<const float4*>(x)[i];
    float4 r;
    r.x = interp_one(v.x);
    r.y = interp_one(v.y);
    r.z = interp_one(v.z);
    r.w = interp_one(v.w);
    reinterpret_cast<float4*>(out)[i] = r;
}

// ---------------------------------------------------------------------------
extern "C" void kernel_launch(void* const* d_in, const int* in_sizes, int n_in,
                              void* d_out, int out_size)
{
    const float* x     = (const float*)d_in[0];
    const float* w_ih1 = (const float*)d_in[1];
    // d_in[2] = w_hh1 (unused: zero state)
    const float* b_ih1 = (const float*)d_in[3];
    const float* b_hh1 = (const float*)d_in[4];
    const float* w_ih2 = (const float*)d_in[5];
    // d_in[6] = w_hh2 (unused)
    const float* b_ih2 = (const float*)d_in[7];
    const float* b_hh2 = (const float*)d_in[8];
    const float* w_lin = (const float*)d_in[9];
    const float* b_lin = (const float*)d_in[10];
    float* out = (float*)d_out;

    const int nblocks_tab = (NT + 31) / 32;          // 257
    build_table_kernel<<<nblocks_tab, 256>>>(w_ih1, b_ih1, b_hh1,
                                             w_ih2, b_ih2, b_hh2,
                                             w_lin, b_lin);

    const int n4 = out_size / 4;                     // 102400 (409600 % 4 == 0)
    interp_kernel<<<(n4 + 255) / 256, 256>>>(x, out, n4);
}